// round 14
// baseline (speedup 1.0000x reference)
#include <cuda_runtime.h>

// IDWT (inverse Haar) — FINAL (confirmed R12/R13 configuration, unchanged).
// Inputs: LL, LH, HL, HH each [B=16, C=64, H2=128, W2=128] fp32.
// Output: [16, 64, 256, 256] fp32.
// out[2i,2j]=a, out[2i,2j+1]=b, out[2i+1,2j]=c, out[2i+1,2j+1]=d where
//   a=(LL+LH+HL+HH)/2, b=(LL+LH-HL-HH)/2, c=(LL-LH+HL-HH)/2, d=(LL-LH-HL+HH)/2
//
// One thread per float2 (2 coefficients). Each thread writes exactly one
// float4 into each of two output rows; consecutive lanes hit consecutive
// float4s -> every STG.128 is a dense 512B warp transaction. Touch-once
// traffic -> .cs streaming policy on all loads/stores.
//
// Measured at the mixed-R/W HBM ceiling: 6.45 TB/s, DRAM ~81%, kernel ~75us.
// Ruled out by isolated A/B tests: store vectorization (v8 STG.256: neutral),
// cache policy (.cs: neutral), granule (float4: neutral), block size
// (256/512: noise), persistent single-wave launch (regression). The DRAM bus
// with 1:1 read/write turnaround is the binding resource; no SM-side pipe
// exceeds 16% utilization.

static constexpr int W2 = 128;                   // input width
static constexpr int H2 = 128;                   // input height
static constexpr int W2F2 = W2 / 2;              // float2 groups per input row = 64
static constexpr int OUT_ROW_F4 = (2 * W2) / 4;  // 64 float4 per output row

static constexpr int BLOCK = 512;

__global__ void __launch_bounds__(BLOCK) idwt_haar_kernel(
    const float2* __restrict__ ll2,
    const float2* __restrict__ lh2,
    const float2* __restrict__ hl2,
    const float2* __restrict__ hh2,
    float4* __restrict__ out4)
{
    unsigned idx = blockIdx.x * BLOCK + threadIdx.x;   // one per 2 input coeffs

    float2 ll = __ldcs(&ll2[idx]);
    float2 lh = __ldcs(&lh2[idx]);
    float2 hl = __ldcs(&hl2[idx]);
    float2 hh = __ldcs(&hh2[idx]);

    float ax, bx, cx, dx, ay, by, cy, dy;
    {
        float s0, s1, d0, d1;
        s0 = ll.x + lh.x; s1 = hl.x + hh.x; d0 = ll.x - lh.x; d1 = hl.x - hh.x;
        ax = 0.5f * (s0 + s1); bx = 0.5f * (s0 - s1);
        cx = 0.5f * (d0 + d1); dx = 0.5f * (d0 - d1);
        s0 = ll.y + lh.y; s1 = hl.y + hh.y; d0 = ll.y - lh.y; d1 = hl.y - hh.y;
        ay = 0.5f * (s0 + s1); by = 0.5f * (s0 - s1);
        cy = 0.5f * (d0 + d1); dy = 0.5f * (d0 - d1);
    }

    // idx = plane*8192 + row*64 + col2 (col2 in [0,64), row in [0,128), plane in [0,1024)).
    unsigned col2  = idx & (W2F2 - 1);        // 0..63
    unsigned row   = (idx >> 6) & (H2 - 1);   // 0..127
    unsigned plane = idx >> 13;               // 0..1023

    // Output base (float4 units): plane*32768 + (2*row)*64 + col2. Max < 2^25.
    unsigned base = plane * (2u * H2 * OUT_ROW_F4)
                  + (2u * row) * OUT_ROW_F4
                  + col2;

    // Row 2i: [a0,b0,a1,b1]; Row 2i+1: [c0,d0,c1,d1] — one dense float4 each.
    __stcs(&out4[base],              make_float4(ax, bx, ay, by));
    __stcs(&out4[base + OUT_ROW_F4], make_float4(cx, dx, cy, dy));
}

extern "C" void kernel_launch(void* const* d_in, const int* in_sizes, int n_in,
                              void* d_out, int out_size)
{
    const float2* ll = (const float2*)d_in[0];
    const float2* lh = (const float2*)d_in[1];
    const float2* hl = (const float2*)d_in[2];
    const float2* hh = (const float2*)d_in[3];
    float4* out = (float4*)d_out;

    int n_groups = in_sizes[0] / 2;              // 2^23
    int grid = (n_groups + BLOCK - 1) / BLOCK;   // 16384
    idwt_haar_kernel<<<grid, BLOCK>>>(ll, lh, hl, hh, out);
}